// round 3
// baseline (speedup 1.0000x reference)
#include <cuda_runtime.h>
#include <math.h>

// Fully fused TreeLSTM cell: no __device__ scratch, smem only.
// N rows (131072), H=D=128, K=4 children. Block = 64 rows, 256 threads.

#define TM       64
#define THREADS  256
#define ES       132   // sEmb row stride (pad: 132 % 32 == 4, float4-aligned)
#define HS       260   // sHio row stride
#define TS       132   // sT   row stride

// smem layout offsets (in floats)
#define OFF_EMB  0
#define OFF_HIO  (OFF_EMB + TM * ES)              // 8448
#define OFF_T    (OFF_HIO + TM * HS)              // 25088
#define OFF_F0   (OFF_T   + TM * TS)              // 33536
#define OFF_C    (OFF_F0  + TM * 128)             // 41728
#define OFF_B    (OFF_C   + TM * 128)             // 49920
#define OFF_NT   (OFF_B   + 16 * 128)             // 51968
#define SMEM_FLOATS (OFF_NT + TM * 4)             // 52224
#define SMEM_BYTES  (SMEM_FLOATS * 4)             // 208896

__device__ __forceinline__ unsigned long long pack2(float lo, float hi)
{
    unsigned long long r;
    asm("mov.b64 %0, {%1, %2};" : "=l"(r)
        : "r"(__float_as_uint(lo)), "r"(__float_as_uint(hi)));
    return r;
}
__device__ __forceinline__ unsigned long long pack_dup(float v)
{
    unsigned long long r;
    unsigned int u = __float_as_uint(v);
    asm("mov.b64 %0, {%1, %1};" : "=l"(r) : "r"(u));
    return r;
}
__device__ __forceinline__ void unpack2(unsigned long long v, float& lo, float& hi)
{
    unsigned int a, b;
    asm("mov.b64 {%0, %1}, %2;" : "=r"(a), "=r"(b) : "l"(v));
    lo = __uint_as_float(a);
    hi = __uint_as_float(b);
}
__device__ __forceinline__ void fma2(unsigned long long& d,
                                     unsigned long long a, unsigned long long b)
{
    asm("fma.rn.f32x2 %0, %1, %2, %0;" : "+l"(d) : "l"(a), "l"(b));
}

// Accumulate C[64x128] += sA[64xKpart] @ Bglob[128 x Kpart]^T into acc (f32x2 pairs).
// acc[i][j]: rows ty4+i, col pair (tx8 + 2j, tx8 + 2j+1) ... j in 0..3 covers 8 cols.
__device__ __forceinline__ void gemm_part(
    unsigned long long acc[4][4],
    const float* __restrict__ Bglob, int ldb, int Kpart,
    const float* sA, int lda, float* sB,
    int tid, int tx8, int ty4)
{
    for (int k0 = 0; k0 < Kpart; k0 += 16) {
        __syncthreads();   // previous consumers of sB done
#pragma unroll
        for (int q = 0; q < 2; q++) {
            int idx = tid * 2 + q;          // 0..511
            int c   = idx >> 2;             // 0..127
            int kq  = (idx & 3) * 4;        // 0,4,8,12
            float4 w = *(const float4*)(Bglob + (size_t)c * ldb + k0 + kq);
            sB[(kq + 0) * 128 + c] = w.x;
            sB[(kq + 1) * 128 + c] = w.y;
            sB[(kq + 2) * 128 + c] = w.z;
            sB[(kq + 3) * 128 + c] = w.w;
        }
        __syncthreads();
#pragma unroll
        for (int kk = 0; kk < 16; kk++) {
            unsigned long long pa[4], pb[4];
#pragma unroll
            for (int i = 0; i < 4; i++)
                pa[i] = pack_dup(sA[(ty4 + i) * lda + k0 + kk]);
            float4 b0 = *(const float4*)(sB + kk * 128 + tx8);
            float4 b1 = *(const float4*)(sB + kk * 128 + tx8 + 4);
            pb[0] = pack2(b0.x, b0.y);
            pb[1] = pack2(b0.z, b0.w);
            pb[2] = pack2(b1.x, b1.y);
            pb[3] = pack2(b1.z, b1.w);
#pragma unroll
            for (int i = 0; i < 4; i++)
#pragma unroll
                for (int j = 0; j < 4; j++)
                    fma2(acc[i][j], pa[i], pb[j]);
        }
    }
}

__device__ __forceinline__ float warp_sum(float v)
{
#pragma unroll
    for (int o = 16; o > 0; o >>= 1) v += __shfl_xor_sync(0xffffffffu, v, o);
    return v;
}

// LayerNorm over 128 values spread 4-per-lane (cols lane, lane+32, lane+64, lane+96).
__device__ __forceinline__ void ln128(float x[4], const float* __restrict__ g,
                                      const float* __restrict__ b, int lane)
{
    float mu = warp_sum(x[0] + x[1] + x[2] + x[3]) * 0.0078125f;
    float c0 = x[0] - mu, c1 = x[1] - mu, c2 = x[2] - mu, c3 = x[3] - mu;
    float q = warp_sum(c0 * c0 + c1 * c1 + c2 * c2 + c3 * c3);
    float rs = rsqrtf(q * 0.0078125f + 1e-5f);
    x[0] = c0 * rs * g[lane]      + b[lane];
    x[1] = c1 * rs * g[lane + 32] + b[lane + 32];
    x[2] = c2 * rs * g[lane + 64] + b[lane + 64];
    x[3] = c3 * rs * g[lane + 96] + b[lane + 96];
}

__device__ __forceinline__ float sigm(float x) { return 1.f / (1.f + expf(-x)); }

__global__ __launch_bounds__(THREADS) void treelstm_fused(
    const float* __restrict__ emb,
    const float* __restrict__ h_child,
    const float* __restrict__ c_child,
    const int*   __restrict__ n_type,
    const float* __restrict__ W_iou,
    const float* __restrict__ U_iou,
    const float* __restrict__ b_iou,
    const float* __restrict__ W_f,
    const float* __restrict__ U_f,
    const float* __restrict__ b_f,
    const float* __restrict__ g_i,  const float* __restrict__ b_i,
    const float* __restrict__ g_o,  const float* __restrict__ b_o,
    const float* __restrict__ g_u,  const float* __restrict__ b_u,
    const float* __restrict__ gn_f, const float* __restrict__ bn_f,
    const float* __restrict__ gn_c, const float* __restrict__ bn_c,
    float* __restrict__ out, int n)
{
    extern __shared__ float sm[];
    float* sEmb = sm + OFF_EMB;
    float* sHio = sm + OFF_HIO;
    float* sT   = sm + OFF_T;
    float* sF0  = sm + OFF_F0;
    float* sC   = sm + OFF_C;
    float* sB   = sm + OFF_B;
    int*   sNT  = (int*)(sm + OFF_NT);

    const int tid  = threadIdx.x;
    const int lane = tid & 31;
    const int wid  = tid >> 5;
    const int tx8  = (tid & 15) * 8;
    const int ty4  = (tid >> 4) * 4;
    const int row0 = blockIdx.x * TM;

    // ---- Phase 0: loads ----
    // n_type tile
    sNT[tid] = n_type[row0 * 4 + tid];                 // 64*4 = 256 entries
    // emb tile (float4)
    for (int e = tid; e < TM * 32; e += THREADS) {     // 32 float4 per row
        int r = e >> 5, c4 = (e & 31) * 4;
        float4 v = *(const float4*)(emb + (size_t)(row0 + r) * 128 + c4);
        *(float4*)(sEmb + r * ES + c4) = v;
    }
    __syncthreads();
    // typed h aggregation -> sHio[r][0:128]=ht0, [128:256]=ht1
    for (int e = tid; e < TM * 128; e += THREADS) {
        int r = e >> 7, c = e & 127;
        const float* hp = h_child + ((size_t)(row0 + r) * 4) * 128 + c;
        float ht0 = 0.f, ht1 = 0.f;
#pragma unroll
        for (int k = 0; k < 4; k++) {
            float h = hp[k * 128];
            if (sNT[r * 4 + k] == 0) ht0 += h; else ht1 += h;
        }
        sHio[r * HS + c]       = ht0;
        sHio[r * HS + 128 + c] = ht1;
    }
    // (sync provided by first barrier inside gemm_part)

    unsigned long long acc[4][4];

#define ZERO_ACC()                                        \
    _Pragma("unroll") for (int i = 0; i < 4; i++)         \
    _Pragma("unroll") for (int j = 0; j < 4; j++) acc[i][j] = 0ull;

#define STORE_T()                                                          \
    __syncthreads();                                                       \
    _Pragma("unroll") for (int i = 0; i < 4; i++) {                        \
        int r = ty4 + i;                                                   \
        float a0, a1, a2, a3;                                              \
        unpack2(acc[i][0], a0, a1); unpack2(acc[i][1], a2, a3);            \
        *(float4*)(sT + r * TS + tx8) = make_float4(a0, a1, a2, a3);       \
        unpack2(acc[i][2], a0, a1); unpack2(acc[i][3], a2, a3);            \
        *(float4*)(sT + r * TS + tx8 + 4) = make_float4(a0, a1, a2, a3);   \
    }                                                                      \
    __syncthreads();

    // ================= Stage 1: u gate =================
    ZERO_ACC();
    gemm_part(acc, W_iou + 256 * 128, 128, 128, sEmb, ES, sB, tid, tx8, ty4);
    gemm_part(acc, U_iou + 256 * 256, 256, 256, sHio, HS, sB, tid, tx8, ty4);
    STORE_T();
    for (int rr = 0; rr < 8; rr++) {
        int r = wid * 8 + rr;
        float x[4];
#pragma unroll
        for (int j = 0; j < 4; j++)
            x[j] = sT[r * TS + lane + 32 * j] + b_iou[256 + lane + 32 * j];
        ln128(x, g_u, b_u, lane);
#pragma unroll
        for (int j = 0; j < 4; j++)
            sF0[r * 128 + lane + 32 * j] = tanhf(x[j]);
    }
    __syncthreads();

    // ================= Stage 2: i gate =================
    ZERO_ACC();
    gemm_part(acc, W_iou, 128, 128, sEmb, ES, sB, tid, tx8, ty4);
    gemm_part(acc, U_iou, 256, 256, sHio, HS, sB, tid, tx8, ty4);
    STORE_T();
    for (int rr = 0; rr < 8; rr++) {
        int r = wid * 8 + rr;
        float x[4];
#pragma unroll
        for (int j = 0; j < 4; j++)
            x[j] = sT[r * TS + lane + 32 * j] + b_iou[lane + 32 * j];
        ln128(x, g_i, b_i, lane);
#pragma unroll
        for (int j = 0; j < 4; j++) {
            int c = lane + 32 * j;
            sC[r * 128 + c] = sigm(x[j]) * sF0[r * 128 + c];
        }
    }
    __syncthreads();

    // ================= Stage 3: f0 =================
    ZERO_ACC();
    gemm_part(acc, W_f, 128, 128, sEmb, ES, sB, tid, tx8, ty4);
    gemm_part(acc, U_f, 256, 256, sHio, HS, sB, tid, tx8, ty4);
    STORE_T();
    for (int rr = 0; rr < 8; rr++) {
        int r = wid * 8 + rr;
        float x[4];
#pragma unroll
        for (int j = 0; j < 4; j++)
            x[j] = sT[r * TS + lane + 32 * j] + b_f[lane + 32 * j];
        ln128(x, gn_f, bn_f, lane);
#pragma unroll
        for (int j = 0; j < 4; j++)
            sF0[r * 128 + lane + 32 * j] = sigm(x[j]);
    }
    __syncthreads();

    // ================= Stage 4: f1 + c_cell combine =================
    ZERO_ACC();
    gemm_part(acc, W_f, 128, 128, sEmb, ES, sB, tid, tx8, ty4);
    gemm_part(acc, U_f + 128 * 256, 256, 256, sHio, HS, sB, tid, tx8, ty4);
    STORE_T();
    for (int rr = 0; rr < 8; rr++) {
        int r = wid * 8 + rr;
        float x[4];
#pragma unroll
        for (int j = 0; j < 4; j++)
            x[j] = sT[r * TS + lane + 32 * j] + b_f[lane + 32 * j];
        ln128(x, gn_f, bn_f, lane);
#pragma unroll
        for (int j = 0; j < 4; j++) {
            int c = lane + 32 * j;
            const float* cp = c_child + ((size_t)(row0 + r) * 4) * 128 + c;
            float ct0 = 0.f, ct1 = 0.f;
#pragma unroll
            for (int k = 0; k < 4; k++) {
                float v = cp[k * 128];
                if (sNT[r * 4 + k] == 0) ct0 += v; else ct1 += v;
            }
            float F0 = sF0[r * 128 + c];
            float F1 = sigm(x[j]);
            sC[r * 128 + c] += F0 * ct0 + F1 * ct1;
        }
    }
    __syncthreads();

    // ================= Stage 5: LN(c), write c out, stash tanh =================
    for (int rr = 0; rr < 8; rr++) {
        int r = wid * 8 + rr;
        float cv[4], x[4];
#pragma unroll
        for (int j = 0; j < 4; j++) {
            cv[j] = sC[r * 128 + lane + 32 * j];
            x[j]  = cv[j];
        }
        ln128(x, gn_c, bn_c, lane);
        float* oc = out + (size_t)n * 128 + (size_t)(row0 + r) * 128;
#pragma unroll
        for (int j = 0; j < 4; j++) {
            int c = lane + 32 * j;
            sF0[r * 128 + c] = tanhf(x[j]);
            oc[c] = cv[j];
        }
    }
    __syncthreads();

    // ================= Stage 6: o gate, write h out =================
    ZERO_ACC();
    gemm_part(acc, W_iou + 128 * 128, 128, 128, sEmb, ES, sB, tid, tx8, ty4);
    gemm_part(acc, U_iou + 128 * 256, 256, 256, sHio, HS, sB, tid, tx8, ty4);
    STORE_T();
    for (int rr = 0; rr < 8; rr++) {
        int r = wid * 8 + rr;
        float x[4];
#pragma unroll
        for (int j = 0; j < 4; j++)
            x[j] = sT[r * TS + lane + 32 * j] + b_iou[128 + lane + 32 * j];
        ln128(x, g_o, b_o, lane);
        float* oh = out + (size_t)(row0 + r) * 128;
#pragma unroll
        for (int j = 0; j < 4; j++) {
            int c = lane + 32 * j;
            oh[c] = sigm(x[j]) * sF0[r * 128 + c];
        }
    }
}

extern "C" void kernel_launch(void* const* d_in, const int* in_sizes, int n_in,
                              void* d_out, int out_size)
{
    const float* emb     = (const float*)d_in[0];
    const float* h_child = (const float*)d_in[1];
    const float* c_child = (const float*)d_in[2];
    const int*   n_type  = (const int*)  d_in[3];
    const float* W_iou   = (const float*)d_in[4];
    const float* U_iou   = (const float*)d_in[5];
    const float* b_iou   = (const float*)d_in[6];
    const float* W_f     = (const float*)d_in[7];
    const float* U_f     = (const float*)d_in[8];
    const float* b_f     = (const float*)d_in[9];
    const float* g_i  = (const float*)d_in[10];
    const float* b_i  = (const float*)d_in[11];
    const float* g_o  = (const float*)d_in[12];
    const float* b_o  = (const float*)d_in[13];
    const float* g_u  = (const float*)d_in[14];
    const float* b_u  = (const float*)d_in[15];
    const float* gn_f = (const float*)d_in[16];
    const float* bn_f = (const float*)d_in[17];
    const float* gn_c = (const float*)d_in[18];
    const float* bn_c = (const float*)d_in[19];
    float* out = (float*)d_out;

    int n = in_sizes[0] / 128;   // N (131072, multiple of 64)

    static int smem_set = 0;
    if (!smem_set) {
        cudaFuncSetAttribute(treelstm_fused,
                             cudaFuncAttributeMaxDynamicSharedMemorySize,
                             SMEM_BYTES);
        smem_set = 1;
    }

    treelstm_fused<<<n / TM, THREADS, SMEM_BYTES>>>(
        emb, h_child, c_child, n_type, W_iou, U_iou, b_iou, W_f, U_f, b_f,
        g_i, b_i, g_o, b_o, g_u, b_u, gn_f, bn_f, gn_c, bn_c, out, n);
}

// round 5
// speedup vs baseline: 1.4055x; 1.4055x over previous
#include <cuda_runtime.h>
#include <math.h>

// Fully fused TreeLSTM cell, register-tiled SGEMM with f32x2 FMA.
// CTA tile: 128 rows x 128 cols, 256 threads, 8x8 microtile per thread.
// A (emb, h_iou) stored k-major in smem; LN done in registers via shuffles.

#define TM      128
#define THREADS 256
#define AS      132          // k-major row stride (floats): 132%32=4, 16B-aligned
#define BK      16

// smem layout (floats)
#define OFF_EMB 0                         // [128 k][AS]  (r in 0..127)
#define OFF_HIO (128 * AS)                // [256 k][AS]
#define OFF_B   (OFF_HIO + 256 * AS)      // double buffer [2][BK][128]
#define OFF_NT  (OFF_B + 2 * BK * 128)    // 512 ints
#define SMEM_FLOATS (OFF_NT + 512)        // 55296
#define SMEM_BYTES  (SMEM_FLOATS * 4)     // 221184

typedef unsigned long long u64;

__device__ __forceinline__ u64 pack2(float lo, float hi)
{
    u64 r;
    asm("mov.b64 %0, {%1, %2};" : "=l"(r)
        : "r"(__float_as_uint(lo)), "r"(__float_as_uint(hi)));
    return r;
}
__device__ __forceinline__ u64 pack_dup(float v)
{
    u64 r;
    unsigned int u = __float_as_uint(v);
    asm("mov.b64 %0, {%1, %1};" : "=l"(r) : "r"(u));
    return r;
}
__device__ __forceinline__ void unpack2(u64 v, float& lo, float& hi)
{
    unsigned int a, b;
    asm("mov.b64 {%0, %1}, %2;" : "=r"(a), "=r"(b) : "l"(v));
    lo = __uint_as_float(a);
    hi = __uint_as_float(b);
}
__device__ __forceinline__ void fma2(u64& d, u64 a, u64 b)
{
    asm("fma.rn.f32x2 %0, %1, %2, %0;" : "+l"(d) : "l"(a), "l"(b));
}

__device__ __forceinline__ float sigm(float x) { return 1.f / (1.f + expf(-x)); }

// One GEMM source: acc += sA(k-major)[K x 128rows] ^T @ W[128c x K]^T slice.
// Double-buffered sB, one __syncthreads per chunk.
__device__ __forceinline__ void gemm_src(
    u64 acc[8][4],
    const float* __restrict__ Wsrc, int ldw, int K,
    const float* sA, float* sB, int tid, int tx8, int ty8)
{
    const int c  = tid >> 1;
    const int kh = (tid & 1) * 8;
    const float* wp = Wsrc + (size_t)c * ldw + kh;

    float4 p0 = __ldg((const float4*)wp);
    float4 p1 = __ldg((const float4*)(wp + 4));
    const int nch = K / BK;

    for (int ch = 0; ch < nch; ch++) {
        float* b = sB + (ch & 1) * (BK * 128);
        b[(kh + 0) * 128 + c] = p0.x;
        b[(kh + 1) * 128 + c] = p0.y;
        b[(kh + 2) * 128 + c] = p0.z;
        b[(kh + 3) * 128 + c] = p0.w;
        b[(kh + 4) * 128 + c] = p1.x;
        b[(kh + 5) * 128 + c] = p1.y;
        b[(kh + 6) * 128 + c] = p1.z;
        b[(kh + 7) * 128 + c] = p1.w;
        if (ch + 1 < nch) {
            p0 = __ldg((const float4*)(wp + (ch + 1) * BK));
            p1 = __ldg((const float4*)(wp + (ch + 1) * BK + 4));
        }
        __syncthreads();
        const float* a = sA + ch * BK * AS;
#pragma unroll
        for (int kk = 0; kk < BK; kk++) {
            float4 a0 = *(const float4*)(a + kk * AS + ty8);
            float4 a1 = *(const float4*)(a + kk * AS + ty8 + 4);
            float4 b0 = *(const float4*)(b + kk * 128 + tx8);
            float4 b1 = *(const float4*)(b + kk * 128 + tx8 + 4);
            u64 pb[4];
            pb[0] = pack2(b0.x, b0.y);
            pb[1] = pack2(b0.z, b0.w);
            pb[2] = pack2(b1.x, b1.y);
            pb[3] = pack2(b1.z, b1.w);
            u64 pa[8];
            pa[0] = pack_dup(a0.x); pa[1] = pack_dup(a0.y);
            pa[2] = pack_dup(a0.z); pa[3] = pack_dup(a0.w);
            pa[4] = pack_dup(a1.x); pa[5] = pack_dup(a1.y);
            pa[6] = pack_dup(a1.z); pa[7] = pack_dup(a1.w);
#pragma unroll
            for (int i = 0; i < 8; i++)
#pragma unroll
                for (int j = 0; j < 4; j++)
                    fma2(acc[i][j], pa[i], pb[j]);
        }
        // no trailing sync: next STS targets the other buffer, and every warp
        // reaching it has passed this chunk's sync (so prior compute on that
        // buffer is globally complete).
    }
}

// In-register LayerNorm over 128 cols: half-warp (16 lanes) holds 8 full rows,
// each lane 8 cols (tx8..tx8+7). xor-shuffle 1,2,4,8 reduces within half-warp.
__device__ __forceinline__ void ln_x(float x[8][8],
                                     const float* __restrict__ g,
                                     const float* __restrict__ b, int tx8)
{
    float4 g0 = __ldg((const float4*)(g + tx8));
    float4 g1 = __ldg((const float4*)(g + tx8 + 4));
    float4 b0 = __ldg((const float4*)(b + tx8));
    float4 b1 = __ldg((const float4*)(b + tx8 + 4));
    float gg[8] = { g0.x, g0.y, g0.z, g0.w, g1.x, g1.y, g1.z, g1.w };
    float bb[8] = { b0.x, b0.y, b0.z, b0.w, b1.x, b1.y, b1.z, b1.w };
#pragma unroll
    for (int i = 0; i < 8; i++) {
        float s = x[i][0] + x[i][1] + x[i][2] + x[i][3]
                + x[i][4] + x[i][5] + x[i][6] + x[i][7];
#pragma unroll
        for (int o = 1; o < 16; o <<= 1) s += __shfl_xor_sync(0xffffffffu, s, o);
        float mu = s * 0.0078125f;
        float q = 0.f;
#pragma unroll
        for (int j = 0; j < 8; j++) {
            x[i][j] -= mu;
            q += x[i][j] * x[i][j];
        }
#pragma unroll
        for (int o = 1; o < 16; o <<= 1) q += __shfl_xor_sync(0xffffffffu, q, o);
        float rs = rsqrtf(q * 0.0078125f + 1e-5f);
#pragma unroll
        for (int j = 0; j < 8; j++)
            x[i][j] = x[i][j] * rs * gg[j] + bb[j];
    }
}

__global__ __launch_bounds__(THREADS) void treelstm_fused(
    const float* __restrict__ emb,
    const float* __restrict__ h_child,
    const float* __restrict__ c_child,
    const int*   __restrict__ n_type,
    const float* __restrict__ W_iou,
    const float* __restrict__ U_iou,
    const float* __restrict__ b_iou,
    const float* __restrict__ W_f,
    const float* __restrict__ U_f,
    const float* __restrict__ b_f,
    const float* __restrict__ g_i,  const float* __restrict__ b_i,
    const float* __restrict__ g_o,  const float* __restrict__ b_o,
    const float* __restrict__ g_u,  const float* __restrict__ b_u,
    const float* __restrict__ gn_f, const float* __restrict__ bn_f,
    const float* __restrict__ gn_c, const float* __restrict__ bn_c,
    float* __restrict__ out, int n)
{
    extern __shared__ float sm[];
    float* sEmb = sm + OFF_EMB;
    float* sHio = sm + OFF_HIO;
    float* sB   = sm + OFF_B;
    int*   sNT  = (int*)(sm + OFF_NT);

    const int tid  = threadIdx.x;
    const int tx8  = (tid & 15) * 8;
    const int ty8  = (tid >> 4) * 8;
    const int row0 = blockIdx.x * TM;

    // ---- Phase 0: n_type, emb (transposed to k-major), typed h aggregation ----
    for (int e = tid; e < 512; e += THREADS)
        sNT[e] = n_type[row0 * 4 + e];

    for (int e = tid; e < 128 * 32; e += THREADS) {     // 32 float4 per row
        int r = e >> 5, k4 = (e & 31) * 4;
        float4 v = __ldg((const float4*)(emb + (size_t)(row0 + r) * 128 + k4));
        sEmb[(k4 + 0) * AS + r] = v.x;
        sEmb[(k4 + 1) * AS + r] = v.y;
        sEmb[(k4 + 2) * AS + r] = v.z;
        sEmb[(k4 + 3) * AS + r] = v.w;
    }
    __syncthreads();   // sNT ready for aggregation

    for (int e = tid; e < 128 * 128; e += THREADS) {
        int c = e & 127, r = e >> 7;
        const float* hp = h_child + ((size_t)(row0 + r) * 4) * 128 + c;
        float h0 = 0.f, h1 = 0.f;
#pragma unroll
        for (int k = 0; k < 4; k++) {
            float h = __ldg(hp + k * 128);
            if (sNT[r * 4 + k] == 0) h0 += h; else h1 += h;
        }
        sHio[c * AS + r]         = h0;
        sHio[(c + 128) * AS + r] = h1;
    }
    __syncthreads();

    u64 acc[8][4];
    float x[8][8];
    float cR[8][8];

#define ZERO_ACC()                                          \
    _Pragma("unroll") for (int i = 0; i < 8; i++)           \
    _Pragma("unroll") for (int j = 0; j < 4; j++) acc[i][j] = 0ull;

#define UNPACK_BIAS(BPTR)                                                  \
    {                                                                      \
        float4 v0 = __ldg((const float4*)((BPTR) + tx8));                  \
        float4 v1 = __ldg((const float4*)((BPTR) + tx8 + 4));              \
        float bv[8] = { v0.x, v0.y, v0.z, v0.w, v1.x, v1.y, v1.z, v1.w };  \
        _Pragma("unroll") for (int i = 0; i < 8; i++) {                    \
            _Pragma("unroll") for (int jp = 0; jp < 4; jp++)               \
                unpack2(acc[i][jp], x[i][2 * jp], x[i][2 * jp + 1]);       \
            _Pragma("unroll") for (int j = 0; j < 8; j++)                  \
                x[i][j] += bv[j];                                          \
        }                                                                  \
    }

    // ================= Stage u =================
    ZERO_ACC();
    gemm_src(acc, W_iou + 256 * 128, 128, 128, sEmb, sB, tid, tx8, ty8);
    gemm_src(acc, U_iou + 256 * 256, 256, 256, sHio, sB, tid, tx8, ty8);
    UNPACK_BIAS(b_iou + 256);
    ln_x(x, g_u, b_u, tx8);
#pragma unroll
    for (int i = 0; i < 8; i++)
#pragma unroll
        for (int j = 0; j < 8; j++) cR[i][j] = tanhf(x[i][j]);

    // ================= Stage i: cR = sigm(i) * tanh(u) =================
    ZERO_ACC();
    gemm_src(acc, W_iou, 128, 128, sEmb, sB, tid, tx8, ty8);
    gemm_src(acc, U_iou, 256, 256, sHio, sB, tid, tx8, ty8);
    UNPACK_BIAS(b_iou);
    ln_x(x, g_i, b_i, tx8);
#pragma unroll
    for (int i = 0; i < 8; i++)
#pragma unroll
        for (int j = 0; j < 8; j++) cR[i][j] *= sigm(x[i][j]);

    // ================= Stage f0: cR += F0 * ct0 =================
    ZERO_ACC();
    gemm_src(acc, W_f, 128, 128, sEmb, sB, tid, tx8, ty8);
    gemm_src(acc, U_f, 256, 256, sHio, sB, tid, tx8, ty8);
    UNPACK_BIAS(b_f);
    ln_x(x, gn_f, bn_f, tx8);
#pragma unroll
    for (int i = 0; i < 8; i++) {
        const float* cc = c_child + ((size_t)(row0 + ty8 + i) * 4) * 128 + tx8;
        float ct[8] = { 0.f, 0.f, 0.f, 0.f, 0.f, 0.f, 0.f, 0.f };
#pragma unroll
        for (int k = 0; k < 4; k++) {
            if (sNT[(ty8 + i) * 4 + k] == 0) {
                float4 v0 = __ldg((const float4*)(cc + k * 128));
                float4 v1 = __ldg((const float4*)(cc + k * 128 + 4));
                ct[0] += v0.x; ct[1] += v0.y; ct[2] += v0.z; ct[3] += v0.w;
                ct[4] += v1.x; ct[5] += v1.y; ct[6] += v1.z; ct[7] += v1.w;
            }
        }
#pragma unroll
        for (int j = 0; j < 8; j++) cR[i][j] += sigm(x[i][j]) * ct[j];
    }

    // ================= Stage f1: cR += F1 * ct1 =================
    ZERO_ACC();
    gemm_src(acc, W_f, 128, 128, sEmb, sB, tid, tx8, ty8);
    gemm_src(acc, U_f + 128 * 256, 256, 256, sHio, sB, tid, tx8, ty8);
    UNPACK_BIAS(b_f);
    ln_x(x, gn_f, bn_f, tx8);
#pragma unroll
    for (int i = 0; i < 8; i++) {
        const float* cc = c_child + ((size_t)(row0 + ty8 + i) * 4) * 128 + tx8;
        float ct[8] = { 0.f, 0.f, 0.f, 0.f, 0.f, 0.f, 0.f, 0.f };
#pragma unroll
        for (int k = 0; k < 4; k++) {
            if (sNT[(ty8 + i) * 4 + k] == 1) {
                float4 v0 = __ldg((const float4*)(cc + k * 128));
                float4 v1 = __ldg((const float4*)(cc + k * 128 + 4));
                ct[0] += v0.x; ct[1] += v0.y; ct[2] += v0.z; ct[3] += v0.w;
                ct[4] += v1.x; ct[5] += v1.y; ct[6] += v1.z; ct[7] += v1.w;
            }
        }
#pragma unroll
        for (int j = 0; j < 8; j++) cR[i][j] += sigm(x[i][j]) * ct[j];
    }

    // ======= write c, then cR := tanh(LN(c)) =======
#pragma unroll
    for (int i = 0; i < 8; i++) {
        float* oc = out + (size_t)n * 128 + (size_t)(row0 + ty8 + i) * 128 + tx8;
        *(float4*)oc       = make_float4(cR[i][0], cR[i][1], cR[i][2], cR[i][3]);
        *(float4*)(oc + 4) = make_float4(cR[i][4], cR[i][5], cR[i][6], cR[i][7]);
#pragma unroll
        for (int j = 0; j < 8; j++) x[i][j] = cR[i][j];
    }
    ln_x(x, gn_c, bn_c, tx8);
#pragma unroll
    for (int i = 0; i < 8; i++)
#pragma unroll
        for (int j = 0; j < 8; j++) cR[i][j] = tanhf(x[i][j]);

    // ================= Stage o: h = sigm(o) * tanh(LN(c)) =================
    ZERO_ACC();
    gemm_src(acc, W_iou + 128 * 128, 128, 128, sEmb, sB, tid, tx8, ty8);
    gemm_src(acc, U_iou + 128 * 256, 256, 256, sHio, sB, tid, tx8, ty8);
    UNPACK_BIAS(b_iou + 128);
    ln_x(x, g_o, b_o, tx8);
#pragma unroll
    for (int i = 0; i < 8; i++) {
        float h[8];
#pragma unroll
        for (int j = 0; j < 8; j++) h[j] = sigm(x[i][j]) * cR[i][j];
        float* oh = out + (size_t)(row0 + ty8 + i) * 128 + tx8;
        *(float4*)oh       = make_float4(h[0], h[1], h[2], h[3]);
        *(float4*)(oh + 4) = make_float4(h[4], h[5], h[6], h[7]);
    }
}

extern "C" void kernel_launch(void* const* d_in, const int* in_sizes, int n_in,
                              void* d_out, int out_size)
{
    const float* emb     = (const float*)d_in[0];
    const float* h_child = (const float*)d_in[1];
    const float* c_child = (const float*)d_in[2];
    const int*   n_type  = (const int*)  d_in[3];
    const float* W_iou   = (const float*)d_in[4];
    const float* U_iou   = (const float*)d_in[5];
    const float* b_iou   = (const float*)d_in[6];
    const float* W_f     = (const float*)d_in[7];
    const float* U_f     = (const float*)d_in[8];
    const float* b_f     = (const float*)d_in[9];
    const float* g_i  = (const float*)d_in[10];
    const float* b_i  = (const float*)d_in[11];
    const float* g_o  = (const float*)d_in[12];
    const float* b_o  = (const float*)d_in[13];
    const float* g_u  = (const float*)d_in[14];
    const float* b_u  = (const float*)d_in[15];
    const float* gn_f = (const float*)d_in[16];
    const float* bn_f = (const float*)d_in[17];
    const float* gn_c = (const float*)d_in[18];
    const float* bn_c = (const float*)d_in[19];
    float* out = (float*)d_out;

    int n = in_sizes[0] / 128;   // N = 131072 (multiple of 128)

    static int smem_set = 0;
    if (!smem_set) {
        cudaFuncSetAttribute(treelstm_fused,
                             cudaFuncAttributeMaxDynamicSharedMemorySize,
                             SMEM_BYTES);
        smem_set = 1;
    }

    treelstm_fused<<<n / TM, THREADS, SMEM_BYTES>>>(
        emb, h_child, c_child, n_type, W_iou, U_iou, b_iou, W_f, U_f, b_f,
        g_i, b_i, g_o, b_o, g_u, b_u, gn_f, bn_f, gn_c, bn_c, out, n);
}